// round 17
// baseline (speedup 1.0000x reference)
#include <cuda_runtime.h>
#include <cuda_fp16.h>
#include <mma.h>
#include <math.h>
#include <string.h>

using namespace nvcuda;

#define NMAX 100000
#define RMAX 3
#define EMAX 1000000

// Scratch (device globals; no allocation allowed)
__device__ __align__(256) float g_z[(size_t)NMAX * 192];             // [N][3][64] final z_r
__device__ __align__(256) __half g_hsrc[(size_t)RMAX * NMAX * 64];   // h_src per relation (fp16)
__device__ __align__(256) float g_el[RMAX * NMAX];                   // el per relation
__device__ __align__(256) float g_er[RMAX * NMAX];                   // er per relation
__device__ __align__(256) int   g_off[RMAX * NMAX + 1];              // CSR row offsets
__device__ __align__(256) int   g_cur[RMAX * NMAX];                  // counts -> fill cursors
__device__ __align__(256) int   g_csr[(size_t)RMAX * EMAX];          // CSR src indices
__device__ __align__(256) int   g_tsum[256];                         // scan tile sums
__device__ __align__(256) float g_wpart[4];                          // semantic logit partials

// ---------- helpers ----------
__device__ __forceinline__ float tanh_approx(float x) {
    float y;
    asm("tanh.approx.f32 %0, %1;" : "=f"(y) : "f"(x));
    return y;
}
__device__ __forceinline__ unsigned int h2_as_u32(__half2 h) {
    unsigned int u;
    memcpy(&u, &h, 4);
    return u;
}
__device__ __forceinline__ __half2 u32_as_h2(unsigned int u) {
    __half2 h;
    memcpy(&h, &u, 4);
    return h;
}

// dynamic smem layout for k_gemm_tc (bytes)
#define SM_A 0
#define SM_B 34816
#define SM_MISC 53248
#define SM_TOTAL 54272
#define LDA 136
#define LDB 72
#define LDC 68

// ---------- WMMA GEMM, 256 threads (+ overlapped CSR fill at blockIdx.y==4) ----------
__global__ __launch_bounds__(256, 3) void k_gemm_tc(
    const float* __restrict__ dst_feat, const float* __restrict__ neigh,
    const float* __restrict__ Wt, const float* __restrict__ bt,
    const float* __restrict__ attn_l, const float* __restrict__ attn_r,
    const int* __restrict__ src, const int* __restrict__ dst,
    int N, int E, int E2, int E3, int nTiles)
{
    extern __shared__ char smem[];
    int tid = threadIdx.x;
    int seg = blockIdx.y;

    if (seg == 4) {
        // ---- CSR fill (ILP-4 batched) ----
        int i0 = (blockIdx.x * 256 + tid) * 4;
        int st = gridDim.x * 256 * 4;
        for (int e = i0; e < E3; e += st) {
            #pragma unroll
            for (int q = 0; q < 4; q++) {
                int ee = e + q;
                if (ee < E3) {
                    int r = (ee >= E2) ? 2 : (ee >= E) ? 1 : 0;
                    int idx = r * N + __ldg(&dst[ee]);
                    int pos = atomicAdd(&g_cur[idx], 1);
                    g_csr[pos] = __ldg(&src[ee]);
                }
            }
        }
        return;
    }

    int wid = tid >> 5;
    __half* As = (__half*)(smem + SM_A);
    __half* Bs = (__half*)(smem + SM_B);
    float*  Cs = (float*)(smem + SM_A);     // aliased with As (warp-private rows)
    float*  bs = (float*)(smem + SM_MISC);
    float*  as_ = (float*)(smem + SM_MISC + 256);

    // ---- W [k=128][n=64] -> fp16 smem (one time) ----
    const float* W = Wt + (size_t)seg * 128 * 64;
    for (int idx = tid; idx < 8192; idx += 256) {
        int k = idx >> 6, n = idx & 63;
        Bs[k * LDB + n] = __float2half(W[idx]);
    }
    if (tid < 64) bs[tid] = bt[seg * 64 + tid];
    int n_av = (seg == 0) ? 3 : 1;
    const float* av = (seg == 0) ? attn_r : (attn_l + (size_t)(seg - 1) * 64);
    for (int i = tid; i < n_av * 64; i += 256) as_[i] = av[i];
    __syncthreads();

    const float4* X4 = (const float4*)((seg == 0) ? dst_feat : (neigh + (size_t)(seg - 1) * N * 128));

    for (int t = blockIdx.x; t < nTiles; t += gridDim.x) {
        int row0 = t * 128;
        // ---- X tile -> fp16 A smem (coalesced; 16 float4/thread) ----
        #pragma unroll 4
        for (int i = 0; i < 16; i++) {
            int idx = i * 256 + tid;
            int row = idx >> 5, c4 = idx & 31;
            int rg = row0 + row;
            if (rg >= N) rg = N - 1;
            float4 f = __ldg(&X4[(size_t)rg * 32 + c4]);
            __half2* dstp = (__half2*)(As + row * LDA + c4 * 4);
            dstp[0] = __floats2half2_rn(f.x, f.y);
            dstp[1] = __floats2half2_rn(f.z, f.w);
        }
        __syncthreads();

        // ---- WMMA: warp computes rows [wid*16, wid*16+16) x 64 cols ----
        wmma::fragment<wmma::accumulator, 16, 16, 16, float> acc[4];
        #pragma unroll
        for (int j = 0; j < 4; j++) wmma::fill_fragment(acc[j], 0.f);

        #pragma unroll
        for (int k0 = 0; k0 < 8; k0++) {
            wmma::fragment<wmma::matrix_a, 16, 16, 16, __half, wmma::row_major> af;
            wmma::load_matrix_sync(af, As + (wid * 16) * LDA + k0 * 16, LDA);
            #pragma unroll
            for (int n0 = 0; n0 < 4; n0++) {
                wmma::fragment<wmma::matrix_b, 16, 16, 16, __half, wmma::row_major> bf;
                wmma::load_matrix_sync(bf, Bs + (k0 * 16) * LDB + n0 * 16, LDB);
                wmma::mma_sync(acc[n0], af, bf, acc[n0]);
            }
        }
        #pragma unroll
        for (int n0 = 0; n0 < 4; n0++)
            wmma::store_matrix_sync(Cs + (wid * 16) * LDC + n0 * 16, acc[n0],
                                    LDC, wmma::mem_row_major);
        __syncthreads();

        // ---- epilogue: 2 threads per row (32 cols each) ----
        int li = tid >> 1, half = tid & 1;
        int row = row0 + li;
        if (row < N) {
            float h[32];
            const float4* cr = (const float4*)(Cs + li * LDC + half * 32);
            const float* bsp = bs + half * 32;
            #pragma unroll
            for (int q = 0; q < 8; q++) {
                float4 f = cr[q];
                h[4 * q + 0] = f.x + bsp[4 * q + 0];
                h[4 * q + 1] = f.y + bsp[4 * q + 1];
                h[4 * q + 2] = f.z + bsp[4 * q + 2];
                h[4 * q + 3] = f.w + bsp[4 * q + 3];
            }
            if (seg > 0) {
                uint4* o4 = (uint4*)(g_hsrc + ((size_t)(seg - 1) * N + row) * 64 + half * 32);
                #pragma unroll
                for (int q = 0; q < 4; q++) {
                    uint4 pk;
                    pk.x = h2_as_u32(__floats2half2_rn(h[8 * q + 0], h[8 * q + 1]));
                    pk.y = h2_as_u32(__floats2half2_rn(h[8 * q + 2], h[8 * q + 3]));
                    pk.z = h2_as_u32(__floats2half2_rn(h[8 * q + 4], h[8 * q + 5]));
                    pk.w = h2_as_u32(__floats2half2_rn(h[8 * q + 6], h[8 * q + 7]));
                    o4[q] = pk;
                }
            }
            for (int v = 0; v < n_av; v++) {
                const float* ap = as_ + v * 64 + half * 32;
                float e = 0.f;
                #pragma unroll
                for (int j = 0; j < 32; j++) e += h[j] * ap[j];
                e += __shfl_xor_sync(0xffffffffu, e, 1);
                if (half == 0) {
                    if (seg == 0) g_er[(size_t)v * N + row] = e;
                    else          g_el[(size_t)(seg - 1) * N + row] = e;
                }
            }
        }
        __syncthreads();
    }
}

// ---------- CSR build: histogram (int4-vectorized dst loads) ----------
__global__ void k_hist(const int* __restrict__ dst, int N, int E, int E2, int E3) {
    int i = blockIdx.x * blockDim.x + threadIdx.x;
    int st = gridDim.x * blockDim.x;
    int n4 = E3 >> 2;
    const int4* d4 = (const int4*)dst;
    for (int q = i; q < n4; q += st) {
        int4 v = __ldg(&d4[q]);
        int e0 = q << 2;
        int r0 = (e0 >= E2) ? 2 : (e0 >= E) ? 1 : 0;
        int r3 = (e0 + 3 >= E2) ? 2 : (e0 + 3 >= E) ? 1 : 0;
        if (r0 == r3) {
            int base = r0 * N;
            atomicAdd(&g_cur[base + v.x], 1);
            atomicAdd(&g_cur[base + v.y], 1);
            atomicAdd(&g_cur[base + v.z], 1);
            atomicAdd(&g_cur[base + v.w], 1);
        } else {
            int es[4] = {v.x, v.y, v.z, v.w};
            #pragma unroll
            for (int k = 0; k < 4; k++) {
                int ee = e0 + k;
                int r = (ee >= E2) ? 2 : (ee >= E) ? 1 : 0;
                atomicAdd(&g_cur[r * N + es[k]], 1);
            }
        }
    }
    for (int e = (n4 << 2) + i; e < E3; e += st) {
        int r = (e >= E2) ? 2 : (e >= E) ? 1 : 0;
        atomicAdd(&g_cur[r * N + __ldg(&dst[e])], 1);
    }
}

// ---------- scan stage A ----------
__global__ void k_scanA(int n) {
    __shared__ int sd[256];
    int tid = threadIdx.x;
    int base = blockIdx.x * 2048 + tid * 8;
    int c[8], pre[8];
    int s = 0;
    #pragma unroll
    for (int i = 0; i < 8; i++) c[i] = (base + i < n) ? g_cur[base + i] : 0;
    #pragma unroll
    for (int i = 0; i < 8; i++) { pre[i] = s; s += c[i]; }
    sd[tid] = s;
    __syncthreads();
    for (int o = 1; o < 256; o <<= 1) {
        int v = (tid >= o) ? sd[tid - o] : 0;
        __syncthreads();
        sd[tid] += v;
        __syncthreads();
    }
    int excl = sd[tid] - s;
    #pragma unroll
    for (int i = 0; i < 8; i++)
        if (base + i < n) g_off[base + i] = excl + pre[i];
    if (tid == 255) g_tsum[blockIdx.x] = sd[255];
}

// ---------- scan stage B+C merged ----------
__global__ void k_scanBC(int n, int total, int nt) {
    __shared__ int sd[256];
    __shared__ int ex[256];
    int tid = threadIdx.x;
    int v = (tid < nt) ? g_tsum[tid] : 0;
    sd[tid] = v;
    __syncthreads();
    for (int o = 1; o < 256; o <<= 1) {
        int x = (tid >= o) ? sd[tid - o] : 0;
        __syncthreads();
        sd[tid] += x;
        __syncthreads();
    }
    ex[tid] = sd[tid] - v;
    __syncthreads();

    int i = blockIdx.x * blockDim.x + tid;
    int st = gridDim.x * blockDim.x;
    for (int j = i; j < n; j += st) {
        int o = g_off[j] + ex[j >> 11];
        g_off[j] = o;
        g_cur[j] = o;
    }
    if (i == 0) {
        g_off[n] = total;
        g_wpart[0] = 0.f; g_wpart[1] = 0.f; g_wpart[2] = 0.f; g_wpart[3] = 0.f;
    }
}

// ---------- aggregate: per (r,dst) gather, 2 edges/iteration ----------
__global__ __launch_bounds__(256) void k_agg(int N) {
    int t = blockIdx.x * blockDim.x + threadIdx.x;
    int g = t >> 4;
    int lane = t & 15;
    int gsz = (gridDim.x * blockDim.x) >> 4;
    int items = 3 * N, N2 = 2 * N;
    const uint2* h2 = (const uint2*)g_hsrc;

    for (int item = g; item < items; item += gsz) {
        int r = (item >= N2) ? 2 : (item >= N) ? 1 : 0;
        int d = item - r * N;
        float er = __ldg(&g_er[item]);
        int j0 = __ldg(&g_off[item]);
        int j1 = __ldg(&g_off[item + 1]);
        const float* elr = g_el + (size_t)r * N;
        const uint2* hr = h2 + (size_t)r * N * 16 + lane;
        float a0 = 0.f, a1 = 0.f, a2 = 0.f, a3 = 0.f, den = 0.f;

        for (int j = j0; j < j1; j += 2) {
            int sA = __ldg(&g_csr[j]);
            bool hasB = (j + 1 < j1);
            int sB = hasB ? __ldg(&g_csr[j + 1]) : sA;
            float elA = __ldg(&elr[sA]);
            uint2 vA = __ldg(&hr[(size_t)sA * 16]);
            float elB = __ldg(&elr[sB]);
            uint2 vB = __ldg(&hr[(size_t)sB * 16]);

            float xA = elA + er;
            float pA = __expf(xA > 0.f ? xA : 0.01f * xA);
            float2 fA0 = __half22float2(u32_as_h2(vA.x));
            float2 fA1 = __half22float2(u32_as_h2(vA.y));
            a0 += pA * fA0.x; a1 += pA * fA0.y; a2 += pA * fA1.x; a3 += pA * fA1.y;
            den += pA;

            if (hasB) {
                float xB = elB + er;
                float pB = __expf(xB > 0.f ? xB : 0.01f * xB);
                float2 fB0 = __half22float2(u32_as_h2(vB.x));
                float2 fB1 = __half22float2(u32_as_h2(vB.y));
                a0 += pB * fB0.x; a1 += pB * fB0.y; a2 += pB * fB1.x; a3 += pB * fB1.y;
                den += pB;
            }
        }
        float dinv = den > 0.f ? 1.f / den : 0.f;   // zero-degree -> elu(0)=0
        a0 *= dinv; a1 *= dinv; a2 *= dinv; a3 *= dinv;
        a0 = a0 > 0.f ? a0 : (__expf(a0) - 1.f);
        a1 = a1 > 0.f ? a1 : (__expf(a1) - 1.f);
        a2 = a2 > 0.f ? a2 : (__expf(a2) - 1.f);
        a3 = a3 > 0.f ? a3 : (__expf(a3) - 1.f);
        *(float4*)(g_z + (size_t)d * 192 + r * 64 + lane * 4) =
            make_float4(a0, a1, a2, a3);
    }
}

// ---------- finalize (WMMA): w logits = mean tanh(z@W1+b1)@w2 per relation ----------
#define FZ_W1 0            // 64 x 136 halfs = 17408
#define FZ_Z  17408        // 64 items x 72 halfs = 9216
#define FZ_C  26624        // 64 x 132 floats = 33792
#define FZ_B1 60416        // 128 f32
#define FZ_W2 60928        // 128 f32
#define FZ_TOTAL 61440
#define FLDW 136
#define FLDZ 72
#define FLDC 132

__global__ void k_finalize_tc(
    const float* __restrict__ W1, const float* __restrict__ b1,
    const float* __restrict__ w2, int N)
{
    extern __shared__ char smem[];
    __half* W1h = (__half*)(smem + FZ_W1);
    __half* Zh  = (__half*)(smem + FZ_Z);
    float*  Cs  = (float*)(smem + FZ_C);
    float*  b1s = (float*)(smem + FZ_B1);
    float*  w2s = (float*)(smem + FZ_W2);
    __shared__ float wsum[4][3];

    int tid = threadIdx.x, wid = tid >> 5, lane = tid & 31;

    for (int idx = tid; idx < 8192; idx += 128) {
        int k = idx >> 7, n = idx & 127;
        W1h[k * FLDW + n] = __float2half(W1[idx]);
    }
    if (tid < 128) { b1s[tid] = b1[tid]; w2s[tid] = w2[tid]; }
    __syncthreads();

    int items = 3 * N, N2 = 2 * N;
    int li = tid >> 1, half = tid & 1;
    float t0 = 0.f, t1 = 0.f, t2 = 0.f;
    int stride = gridDim.x * 64;

    for (int item0 = blockIdx.x * 64; item0 < items; item0 += stride) {
        {
            int it = item0 + li;
            int iu = (it < items) ? it : 0;
            int r = (iu >= N2) ? 2 : (iu >= N) ? 1 : 0;
            int row = iu - r * N;
            const float4* zr = (const float4*)(g_z + (size_t)row * 192 + r * 64) + half * 8;
            __half2* zd = (__half2*)(Zh + li * FLDZ + half * 32);
            #pragma unroll
            for (int q = 0; q < 8; q++) {
                float4 f = zr[q];
                zd[2 * q + 0] = __floats2half2_rn(f.x, f.y);
                zd[2 * q + 1] = __floats2half2_rn(f.z, f.w);
            }
        }
        __syncthreads();

        {
            wmma::fragment<wmma::accumulator, 16, 16, 16, float> acc[8];
            #pragma unroll
            for (int j = 0; j < 8; j++) wmma::fill_fragment(acc[j], 0.f);
            #pragma unroll
            for (int k0 = 0; k0 < 4; k0++) {
                wmma::fragment<wmma::matrix_a, 16, 16, 16, __half, wmma::row_major> af;
                wmma::load_matrix_sync(af, Zh + (wid * 16) * FLDZ + k0 * 16, FLDZ);
                #pragma unroll
                for (int n0 = 0; n0 < 8; n0++) {
                    wmma::fragment<wmma::matrix_b, 16, 16, 16, __half, wmma::row_major> bf;
                    wmma::load_matrix_sync(bf, W1h + (k0 * 16) * FLDW + n0 * 16, FLDW);
                    wmma::mma_sync(acc[n0], af, bf, acc[n0]);
                }
            }
            #pragma unroll
            for (int n0 = 0; n0 < 8; n0++)
                wmma::store_matrix_sync(Cs + (wid * 16) * FLDC + n0 * 16, acc[n0],
                                        FLDC, wmma::mem_row_major);
        }
        __syncthreads();

        {
            int it = item0 + li;
            if (it < items) {
                int r = (it >= N2) ? 2 : (it >= N) ? 1 : 0;
                const float* cr = Cs + li * FLDC + half * 64;
                const float* b1p = b1s + half * 64;
                const float* w2p = w2s + half * 64;
                float s = 0.f;
                #pragma unroll 16
                for (int c = 0; c < 64; c++)
                    s += tanh_approx(cr[c] + b1p[c]) * w2p[c];
                s += __shfl_xor_sync(0xffffffffu, s, 1);
                if (half == 0) {
                    if (r == 0) t0 += s; else if (r == 1) t1 += s; else t2 += s;
                }
            }
        }
        __syncthreads();
    }

    #pragma unroll
    for (int o = 16; o; o >>= 1) {
        t0 += __shfl_xor_sync(0xffffffffu, t0, o);
        t1 += __shfl_xor_sync(0xffffffffu, t1, o);
        t2 += __shfl_xor_sync(0xffffffffu, t2, o);
    }
    if (lane == 0) { wsum[wid][0] = t0; wsum[wid][1] = t1; wsum[wid][2] = t2; }
    __syncthreads();
    if (tid < 3) {
        float s = 0.f;
        #pragma unroll
        for (int w = 0; w < 4; w++) s += wsum[w][tid];
        atomicAdd(&g_wpart[tid], s);
    }
}

// ---------- semantic softmax + mix ----------
__global__ void k_mix(float* __restrict__ out, int N, float invN) {
    float w0 = g_wpart[0] * invN, w1 = g_wpart[1] * invN, w2v = g_wpart[2] * invN;
    float m = fmaxf(w0, fmaxf(w1, w2v));
    float e0 = __expf(w0 - m), e1 = __expf(w1 - m), e2 = __expf(w2v - m);
    float si = 1.f / (e0 + e1 + e2);
    float a0 = e0 * si, a1 = e1 * si, a2 = e2 * si;

    const float4* z4 = (const float4*)g_z;
    float4* o4 = (float4*)out;
    int total = N * 16;
    int i = blockIdx.x * blockDim.x + threadIdx.x;
    int stride = gridDim.x * blockDim.x;
    for (int idx = i; idx < total; idx += stride) {
        int n = idx >> 4, q = idx & 15;
        float4 v0 = z4[(size_t)n * 48 + q];
        float4 v1 = z4[(size_t)n * 48 + 16 + q];
        float4 v2 = z4[(size_t)n * 48 + 32 + q];
        float4 o;
        o.x = a0 * v0.x + a1 * v1.x + a2 * v2.x;
        o.y = a0 * v0.y + a1 * v1.y + a2 * v2.y;
        o.z = a0 * v0.z + a1 * v1.z + a2 * v2.z;
        o.w = a0 * v0.w + a1 * v1.w + a2 * v2.w;
        o4[idx] = o;
    }
}

extern "C" void kernel_launch(void* const* d_in, const int* in_sizes, int n_in,
                              void* d_out, int out_size) {
    const float* dst_feat = (const float*)d_in[0];
    const float* neigh    = (const float*)d_in[1];
    const float* Wt       = (const float*)d_in[2];
    const float* bt       = (const float*)d_in[3];
    const float* attn_l   = (const float*)d_in[4];
    const float* attn_r   = (const float*)d_in[5];
    const float* W1       = (const float*)d_in[6];
    const float* b1       = (const float*)d_in[7];
    const float* w2       = (const float*)d_in[8];
    const int*   src      = (const int*)d_in[9];
    const int*   dst      = (const int*)d_in[10];

    int N = in_sizes[0] / 128;          // 100000
    int E = in_sizes[9] / 3;            // 1000000
    int E2 = 2 * E, E3 = 3 * E;
    int n3 = 3 * N;
    int nScanTiles = (n3 + 2047) / 2048;   // 147 <= 256
    int nTiles = (N + 127) / 128;          // 782 row tiles
    (void)n_in; (void)out_size;

    void* cp = nullptr;
    cudaGetSymbolAddress(&cp, g_cur);
    cudaMemsetAsync(cp, 0, (size_t)n3 * sizeof(int));

    k_hist<<<1184, 256>>>(dst, N, E, E2, E3);
    k_scanA<<<nScanTiles, 256>>>(n3);
    k_scanBC<<<(n3 + 255) / 256, 256>>>(n3, E3, nScanTiles);

    // WMMA GEMMs + CSR fill in one launch — 4th kernel (ncu capture target)
    cudaFuncSetAttribute(k_gemm_tc, cudaFuncAttributeMaxDynamicSharedMemorySize, SM_TOTAL);
    dim3 ggrid(148, 5);
    k_gemm_tc<<<ggrid, 256, SM_TOTAL>>>(dst_feat, neigh, Wt, bt, attn_l, attn_r,
                                        src, dst, N, E, E2, E3, nTiles);

    k_agg<<<1184, 256>>>(N);

    cudaFuncSetAttribute(k_finalize_tc, cudaFuncAttributeMaxDynamicSharedMemorySize, FZ_TOTAL);
    k_finalize_tc<<<444, 128, FZ_TOTAL>>>(W1, b1, w2, N);

    k_mix<<<1024, 256>>>((float*)d_out, N, 1.0f / (float)N);
}